// round 9
// baseline (speedup 1.0000x reference)
#include <cuda_runtime.h>
#include <math.h>
#include <stdint.h>
#include <stddef.h>

// ---------------------------------------------------------------------------
// SpeechTopKDecoder: T=64-step beam-search decoder. fp32 throughout.
// R9: persistent decode loop with FAST monotone atomic-counter grid barrier
//     (1 atomicAdd per block per barrier; no scan, no sleep). Phase code is
//     byte-identical to R7 (R4 GEMM internals, 6x8 tiles). 4 launches total.
// Deterministic: fixed-order split-K reductions, no float atomics.
// ---------------------------------------------------------------------------

#define Bb   16
#define Kb   3
#define Sx   512
#define Hx   1024
#define Cx   2000
#define Tx   64
#define NHx  4
#define DHx  256
#define BKx  48
#define NEGV (-1000000000.0f)
#define SOSv 1
#define EOSv 2

#define SPL 8    // lstm split-K
#define SPQ 32   // q / p split-K
#define SPG 16   // wg split-K

// ------------------------------ device scratch ------------------------------
__device__ float g_kT [(size_t)Bb * NHx * DHx * Sx];   // keys   (B,NH,DH,S)
__device__ float g_vv [(size_t)Bb * NHx * Sx * DHx];   // values (B,NH,S,DH)
__device__ float g_h  [2 * BKx * Hx];
__device__ float g_c  [2 * BKx * Hx];
__device__ float g_hs [2 * BKx * Hx];
__device__ float g_cs [2 * BKx * Hx];
__device__ float g_gatesP[(size_t)SPL * BKx * 4096];
__device__ float g_qP [(size_t)SPQ * BKx * Hx];
__device__ float g_pP [(size_t)SPQ * BKx * Hx];
__device__ float g_gP [(size_t)SPG * BKx * 2048];
__device__ float g_ctx [BKx * Hx];
__device__ float g_out1[BKx * Hx];
__device__ float g_tanh[BKx * Hx];
__device__ float g_cand[BKx * Cx];
__device__ float g_score[BKx];
__device__ int   g_inp [BKx];

// grid-barrier state (monotone counter; reset only by init_kernel per replay)
__device__ unsigned g_cnt;
__device__ volatile unsigned g_rel;

// ------------------------------ shared layouts ------------------------------
struct SmemLstm { float As[32][49]; float Bs[256][33]; int sIdx[48]; };
struct SmemKN   { float As[32][49]; float Bs[32][264]; };
struct SmemAttn { float q[3][256]; float att[3][512]; float red[8]; float inv[3]; };
struct SmemLN   { float y[Hx]; float red[8]; };
struct SmemLSM  { float sl[Cx]; float red[8]; };
struct SmemTopK { float rv[8]; int ri[8]; int chI[3]; float chV[3]; };

// ------------------------------ helpers -------------------------------------
__device__ __forceinline__ float warpMax(float v) {
#pragma unroll
    for (int o = 16; o; o >>= 1) v = fmaxf(v, __shfl_xor_sync(0xffffffffu, v, o));
    return v;
}
__device__ __forceinline__ float warpSum(float v) {
#pragma unroll
    for (int o = 16; o; o >>= 1) v += __shfl_xor_sync(0xffffffffu, v, o);
    return v;
}
__device__ __forceinline__ float blockMax(float v, volatile float* red, int tid) {
    v = warpMax(v);
    if ((tid & 31) == 0) red[tid >> 5] = v;
    __syncthreads();
    float r = red[0];
#pragma unroll
    for (int w = 1; w < 8; w++) r = fmaxf(r, red[w]);
    __syncthreads();
    return r;
}
__device__ __forceinline__ float blockSum(float v, volatile float* red, int tid) {
    v = warpSum(v);
    if ((tid & 31) == 0) red[tid >> 5] = v;
    __syncthreads();
    float r = red[0];
#pragma unroll
    for (int w = 1; w < 8; w++) r += red[w];
    __syncthreads();
    return r;
}
__device__ __forceinline__ float sigf(float x) { return 1.0f / (1.0f + expf(-x)); }

// fast grid barrier: one atomicAdd per block; monotone count (no reset race).
// gen must increment by exactly 1 per barrier, starting at 1.
__device__ __forceinline__ void gsync(unsigned nb, unsigned gen) {
    __syncthreads();
    if (threadIdx.x == 0) {
        __threadfence();
        unsigned prev = atomicAdd(&g_cnt, 1u);
        if (prev + 1u == nb * gen) {
            __threadfence();
            g_rel = gen;
        }
        while (g_rel < gen) { }
        __threadfence();
    }
    __syncthreads();
}

// ------------------------------ init ----------------------------------------
__global__ void init_kernel() {
    int idx = blockIdx.x * 256 + threadIdx.x;
    if (idx < 2 * BKx * Hx) { g_h[idx] = 0.0f; g_c[idx] = 0.0f; }
    if (idx < BKx) {
        g_score[idx] = (idx % Kb == 0) ? 0.0f : NEGV;
        g_inp[idx] = SOSv;
    }
    if (idx == 0) { g_cnt = 0; g_rel = 0; }
}

// ------------------------------ K/V projection (standalone) -----------------
__global__ void __launch_bounds__(256)
kvproj_kernel(const float* __restrict__ enc, const float* __restrict__ W,
              const float* __restrict__ bias, int z) {
    __shared__ float As[16][132];
    __shared__ float Bs[16][132];
    const int tid = threadIdx.x;
    const int tx = tid & 15, ty = tid >> 4;
    const int n0 = blockIdx.x * 128;
    const int m0 = blockIdx.y * 128;

    const int ak4 = tid & 3,  am = tid >> 2;
    const int bn4 = tid & 31, bkk = tid >> 5;

    float4 aR[2], bR[2];
    float acc[8][8];
#pragma unroll
    for (int i = 0; i < 8; i++)
#pragma unroll
        for (int j = 0; j < 8; j++) acc[i][j] = 0.0f;

#define KV_LOAD(kb)                                                            \
    {                                                                          \
        aR[0] = *(const float4*)(enc + (size_t)(m0 + am) * Hx + (kb) + ak4*4); \
        aR[1] = *(const float4*)(enc + (size_t)(m0 + 64 + am) * Hx + (kb) + ak4*4); \
        bR[0] = *(const float4*)(W + (size_t)((kb) + bkk) * Hx + n0 + bn4*4);  \
        bR[1] = *(const float4*)(W + (size_t)((kb) + 8 + bkk) * Hx + n0 + bn4*4); \
    }
#define KV_STORE()                                                             \
    {                                                                          \
        float av0[4] = {aR[0].x, aR[0].y, aR[0].z, aR[0].w};                   \
        float av1[4] = {aR[1].x, aR[1].y, aR[1].z, aR[1].w};                   \
        _Pragma("unroll")                                                      \
        for (int j = 0; j < 4; j++) {                                          \
            As[ak4*4 + j][am]      = av0[j];                                   \
            As[ak4*4 + j][64 + am] = av1[j];                                   \
        }                                                                      \
        *(float4*)&Bs[bkk][bn4*4]     = bR[0];                                 \
        *(float4*)&Bs[8 + bkk][bn4*4] = bR[1];                                 \
    }

    KV_LOAD(0);
#pragma unroll 1
    for (int t = 0; t < Hx / 16; t++) {
        __syncthreads();
        KV_STORE();
        __syncthreads();
        if (t + 1 < Hx / 16) KV_LOAD((t + 1) * 16);
#pragma unroll 2
        for (int kk = 0; kk < 16; kk++) {
            float a[8], b[8];
#pragma unroll
            for (int r = 0; r < 8; r++) a[r] = As[kk][ty + 16 * r];
#pragma unroll
            for (int k = 0; k < 8; k++) b[k] = Bs[kk][tx + 16 * k];
#pragma unroll
            for (int r = 0; r < 8; r++)
#pragma unroll
                for (int k = 0; k < 8; k++) acc[r][k] = fmaf(a[r], b[k], acc[r][k]);
        }
    }

#pragma unroll
    for (int r = 0; r < 8; r++) {
        int gm = m0 + ty + 16 * r;
        int b = gm >> 9, s = gm & 511;
#pragma unroll
        for (int k = 0; k < 8; k++) {
            int col = n0 + tx + 16 * k;
            int h = col >> 8, d = col & 255;
            float v = acc[r][k] + bias[col];
            if (z == 0)
                g_kT[(((size_t)b * NHx + h) * DHx + d) * Sx + s] = v;
            else
                g_vv[(((size_t)b * NHx + h) * Sx + s) * DHx + d] = v;
        }
    }
#undef KV_LOAD
#undef KV_STORE
}

// ------------------------------ phase: LSTM GEMM ----------------------------
__device__ void d_gemm_lstm(int v, char* smemRaw,
                            const float* A0, const int* aidx, const float* B0,
                            const float* A1, const float* B1,
                            int kPerSplit, float* Cpart) {
    SmemLstm& s = *reinterpret_cast<SmemLstm*>(smemRaw);
    const int tid = threadIdx.x;
    const int tx = tid & 31, ty = tid >> 5;
    const int n0 = (v & 15) * 256;
    const int sp = v >> 4;
    const int k0 = sp * kPerSplit;

    if (aidx != nullptr && tid < 48) s.sIdx[tid] = aidx[tid];

    const int bk4 = tid & 7;
    const int bn  = tid >> 3;
    const int tpp = kPerSplit >> 5;
    const int ntiles = tpp * 2;

    float4 bR[8];
    float4 aR[2];
    float acc[6][8];
#pragma unroll
    for (int i = 0; i < 6; i++)
#pragma unroll
        for (int j = 0; j < 8; j++) acc[i][j] = 0.0f;

    __syncthreads();  // sIdx visible

#define LS_LOAD(t)                                                             \
    {                                                                          \
        int pair = (t) / tpp;                                                  \
        int kb = k0 + ((t) - pair * tpp) * 32;                                 \
        const float* A = pair ? A1 : A0;                                       \
        const float* B = pair ? B1 : B0;                                       \
        bool gat = (pair == 0) && (aidx != nullptr);                           \
        _Pragma("unroll")                                                      \
        for (int r = 0; r < 8; r++)                                            \
            bR[r] = *(const float4*)(B + (size_t)(n0 + bn + 32*r) * Hx + kb + bk4*4); \
        int r0 = gat ? s.sIdx[bn] : bn;                                        \
        aR[0] = *(const float4*)(A + (size_t)r0 * Hx + kb + bk4*4);            \
        if (bn < 16) {                                                         \
            int r1 = gat ? s.sIdx[32 + bn] : (32 + bn);                        \
            aR[1] = *(const float4*)(A + (size_t)r1 * Hx + kb + bk4*4);        \
        }                                                                      \
    }
#define LS_STORE()                                                             \
    {                                                                          \
        _Pragma("unroll")                                                      \
        for (int r = 0; r < 8; r++) {                                          \
            float bv[4] = {bR[r].x, bR[r].y, bR[r].z, bR[r].w};                \
            _Pragma("unroll")                                                  \
            for (int j = 0; j < 4; j++) s.Bs[bn + 32*r][bk4*4 + j] = bv[j];    \
        }                                                                      \
        float av0[4] = {aR[0].x, aR[0].y, aR[0].z, aR[0].w};                   \
        _Pragma("unroll")                                                      \
        for (int j = 0; j < 4; j++) s.As[bk4*4 + j][bn] = av0[j];              \
        if (bn < 16) {                                                         \
            float av1[4] = {aR[1].x, aR[1].y, aR[1].z, aR[1].w};               \
            _Pragma("unroll")                                                  \
            for (int j = 0; j < 4; j++) s.As[bk4*4 + j][32 + bn] = av1[j];     \
        }                                                                      \
    }

    LS_LOAD(0);
#pragma unroll 1
    for (int t = 0; t < ntiles; t++) {
        __syncthreads();
        LS_STORE();
        __syncthreads();
        if (t + 1 < ntiles) LS_LOAD(t + 1);
#pragma unroll 4
        for (int kk = 0; kk < 32; kk++) {
            float a[6];
#pragma unroll
            for (int r = 0; r < 6; r++) a[r] = s.As[kk][ty * 6 + r];
#pragma unroll
            for (int k = 0; k < 8; k++) {
                float b = s.Bs[tx + 32 * k][kk];
#pragma unroll
                for (int r = 0; r < 6; r++) acc[r][k] = fmaf(a[r], b, acc[r][k]);
            }
        }
    }

    float* Cb = Cpart + ((size_t)sp * 48 + ty * 6) * 4096 + n0 + tx;
#pragma unroll
    for (int r = 0; r < 6; r++)
#pragma unroll
        for (int k = 0; k < 8; k++) Cb[(size_t)r * 4096 + 32 * k] = acc[r][k];
#undef LS_LOAD
#undef LS_STORE
}

// ------------------------------ phase: KN GEMM ------------------------------
__device__ void d_gemm_kn(int v, int ntShift, char* smemRaw,
                          const float* A, const float* B,
                          int kPerSplit, int Nreal, int Nstride, float* Cpart) {
    SmemKN& s = *reinterpret_cast<SmemKN*>(smemRaw);
    const int tid = threadIdx.x;
    const int tx = tid & 31, ty = tid >> 5;
    const int n0 = (v & ((1 << ntShift) - 1)) * 256;
    const int sp = v >> ntShift;
    const int k0 = sp * kPerSplit;

    const int ak4 = tid & 7, am = tid >> 3;
    const int bn4 = tid & 63, bkk = tid >> 6;

    const int ntiles = kPerSplit >> 5;

    float4 bR[8];
    float4 aR[2];
    float acc[6][8];
#pragma unroll
    for (int i = 0; i < 6; i++)
#pragma unroll
        for (int j = 0; j < 8; j++) acc[i][j] = 0.0f;

    __syncthreads();  // smem handoff from previous phase

#define KN_LOAD(kb)                                                            \
    {                                                                          \
        int col = n0 + bn4 * 4;                                                \
        _Pragma("unroll")                                                      \
        for (int r = 0; r < 8; r++) {                                          \
            bR[r] = (col < Nreal)                                              \
                ? *(const float4*)(B + (size_t)((kb) + bkk + 4*r) * Nreal + col) \
                : make_float4(0.f, 0.f, 0.f, 0.f);                             \
        }                                                                      \
        aR[0] = *(const float4*)(A + (size_t)am * Hx + (kb) + ak4*4);          \
        if (am < 16)                                                           \
            aR[1] = *(const float4*)(A + (size_t)(32 + am) * Hx + (kb) + ak4*4); \
    }
#define KN_STORE()                                                             \
    {                                                                          \
        _Pragma("unroll")                                                      \
        for (int r = 0; r < 8; r++) *(float4*)&s.Bs[bkk + 4*r][bn4*4] = bR[r]; \
        float av0[4] = {aR[0].x, aR[0].y, aR[0].z, aR[0].w};                   \
        _Pragma("unroll")                                                      \
        for (int j = 0; j < 4; j++) s.As[ak4*4 + j][am] = av0[j];              \
        if (am < 16) {                                                         \
            float av1[4] = {aR[1].x, aR[1].y, aR[1].z, aR[1].w};               \
            _Pragma("unroll")                                                  \
            for (int j = 0; j < 4; j++) s.As[ak4*4 + j][32 + am] = av1[j];     \
        }                                                                      \
    }

    KN_LOAD(k0);
#pragma unroll 1
    for (int t = 0; t < ntiles; t++) {
        __syncthreads();
        KN_STORE();
        __syncthreads();
        if (t + 1 < ntiles) KN_LOAD(k0 + (t + 1) * 32);
#pragma unroll 4
        for (int kk = 0; kk < 32; kk++) {
            float a[6];
#pragma unroll
            for (int r = 0; r < 6; r++) a[r] = s.As[kk][ty * 6 + r];
#pragma unroll
            for (int k = 0; k < 8; k++) {
                float b = s.Bs[kk][tx + 32 * k];
#pragma unroll
                for (int r = 0; r < 6; r++) acc[r][k] = fmaf(a[r], b, acc[r][k]);
            }
        }
    }

    float* Cb = Cpart + ((size_t)sp * 48 + ty * 6) * Nstride + n0 + tx;
#pragma unroll
    for (int r = 0; r < 6; r++)
#pragma unroll
        for (int k = 0; k < 8; k++) Cb[(size_t)r * Nstride + 32 * k] = acc[r][k];
#undef KN_LOAD
#undef KN_STORE
}

// ------------------------------ phase: LSTM pointwise -----------------------
__device__ void d_point(int NB, int layer, const float* bih, const float* bhh) {
    for (int idx = blockIdx.x * 256 + threadIdx.x; idx < BKx * Hx; idx += NB * 256) {
        int bk = idx >> 10, n = idx & 1023;
        float iv = 0.f, fv = 0.f, gv = 0.f, ov = 0.f;
#pragma unroll
        for (int p = 0; p < SPL; p++) {
            const float* r = g_gatesP + ((size_t)p * BKx + bk) * 4096;
            iv += r[n]; fv += r[n + 1024]; gv += r[n + 2048]; ov += r[n + 3072];
        }
        iv += bih[n]        + bhh[n];
        fv += bih[n + 1024] + bhh[n + 1024];
        gv += bih[n + 2048] + bhh[n + 2048];
        ov += bih[n + 3072] + bhh[n + 3072];
        size_t off = ((size_t)layer * BKx + bk) * Hx + n;
        float cp = g_c[off];
        float cn = sigf(fv) * cp + sigf(iv) * tanhf(gv);
        float hn = sigf(ov) * tanhf(cn);
        g_cs[off] = cn;
        g_hs[off] = hn;
    }
}

// ------------------------------ phase: attention ----------------------------
__device__ void d_attn(int v, char* smemRaw, const float* bq) {
    SmemAttn& s = *reinterpret_cast<SmemAttn*>(smemRaw);
    const int b = v >> 2, h = v & 3, tid = threadIdx.x;
    __syncthreads();

    for (int e = tid; e < 3 * 256; e += 256) {
        int kb = e >> 8, d = e & 255;
        int col = h * 256 + d, row = b * 3 + kb;
        float val = bq[col];
#pragma unroll
        for (int p = 0; p < SPQ; p++) val += g_qP[((size_t)p * BKx + row) * Hx + col];
        s.q[kb][d] = val;
    }
    __syncthreads();

    const float* kbase = g_kT + ((size_t)(b * NHx + h) * DHx) * Sx;
#pragma unroll
    for (int r = 0; r < 2; r++) {
        int sidx = tid + r * 256;
        float a0 = 0.f, a1 = 0.f, a2 = 0.f;
#pragma unroll 4
        for (int d = 0; d < 256; d++) {
            float kv = kbase[(size_t)d * Sx + sidx];
            a0 += s.q[0][d] * kv; a1 += s.q[1][d] * kv; a2 += s.q[2][d] * kv;
        }
        const float sc = 1.0f / 16.0f;
        s.att[0][sidx] = a0 * sc; s.att[1][sidx] = a1 * sc; s.att[2][sidx] = a2 * sc;
    }
    __syncthreads();

#pragma unroll
    for (int kb = 0; kb < 3; kb++) {
        float m = fmaxf(s.att[kb][tid], s.att[kb][tid + 256]);
        m = blockMax(m, s.red, tid);
        float e0 = expf(s.att[kb][tid] - m);
        float e1 = expf(s.att[kb][tid + 256] - m);
        s.att[kb][tid] = e0; s.att[kb][tid + 256] = e1;
        __syncthreads();
        float sm = blockSum(e0 + e1, s.red, tid);
        if (tid == 0) s.inv[kb] = 1.0f / sm;
    }
    __syncthreads();

    const int d = tid;
    const float* vbase = g_vv + ((size_t)(b * NHx + h) * Sx) * DHx + d;
    float c0 = 0.f, c1 = 0.f, c2 = 0.f;
#pragma unroll 4
    for (int sidx = 0; sidx < Sx; sidx++) {
        float vv = vbase[(size_t)sidx * DHx];
        c0 += s.att[0][sidx] * vv; c1 += s.att[1][sidx] * vv; c2 += s.att[2][sidx] * vv;
    }
    g_ctx[(size_t)(b * 3 + 0) * Hx + h * 256 + d] = c0 * s.inv[0];
    g_ctx[(size_t)(b * 3 + 1) * Hx + h * 256 + d] = c1 * s.inv[1];
    g_ctx[(size_t)(b * 3 + 2) * Hx + h * 256 + d] = c2 * s.inv[2];
}

// ------------------------------ phase: layernorms ---------------------------
__device__ void d_ln1(int v, char* smemRaw, const float* g1, const float* b1) {
    SmemLN& s = *reinterpret_cast<SmemLN*>(smemRaw);
    const int bk = v, tid = threadIdx.x;
    __syncthreads();
    float loc = 0.f;
#pragma unroll
    for (int j = 0; j < 4; j++) {
        int n = tid + j * 256;
        float val = g_ctx[(size_t)bk * Hx + n] + g_hs[((size_t)1 * BKx + bk) * Hx + n];
        s.y[n] = val; loc += val;
    }
    float mean = blockSum(loc, s.red, tid) * (1.0f / Hx);
    float loc2 = 0.f;
#pragma unroll
    for (int j = 0; j < 4; j++) {
        int n = tid + j * 256;
        float d = s.y[n] - mean; loc2 += d * d;
    }
    float var = blockSum(loc2, s.red, tid) * (1.0f / Hx);
    float w = rsqrtf(var + 1e-5f);
#pragma unroll
    for (int j = 0; j < 4; j++) {
        int n = tid + j * 256;
        g_out1[(size_t)bk * Hx + n] = (s.y[n] - mean) * w * g1[n] + b1[n];
    }
}

__device__ void d_ln2(int v, char* smemRaw, const float* bp,
                      const float* g2, const float* b2) {
    SmemLN& s = *reinterpret_cast<SmemLN*>(smemRaw);
    const int bk = v, tid = threadIdx.x;
    __syncthreads();
    float loc = 0.f;
#pragma unroll
    for (int j = 0; j < 4; j++) {
        int n = tid + j * 256;
        float val = bp[n] + g_out1[(size_t)bk * Hx + n];
#pragma unroll
        for (int p = 0; p < SPQ; p++) val += g_pP[((size_t)p * BKx + bk) * Hx + n];
        s.y[n] = val; loc += val;
    }
    float mean = blockSum(loc, s.red, tid) * (1.0f / Hx);
    float loc2 = 0.f;
#pragma unroll
    for (int j = 0; j < 4; j++) {
        int n = tid + j * 256;
        float d = s.y[n] - mean; loc2 += d * d;
    }
    float var = blockSum(loc2, s.red, tid) * (1.0f / Hx);
    float w = rsqrtf(var + 1e-5f);
#pragma unroll
    for (int j = 0; j < 4; j++) {
        int n = tid + j * 256;
        g_tanh[(size_t)bk * Hx + n] = tanhf((s.y[n] - mean) * w * g2[n] + b2[n]);
    }
}

// ------------------------------ phase: log-softmax --------------------------
__device__ void d_lsm(int v, char* smemRaw, float* out, int step) {
    SmemLSM& s = *reinterpret_cast<SmemLSM*>(smemRaw);
    const int bk = v, tid = threadIdx.x;
    __syncthreads();
    float m = -INFINITY;
    for (int c = tid; c < Cx; c += 256) {
        float val = 0.f;
#pragma unroll
        for (int p = 0; p < SPG; p++) val += g_gP[((size_t)p * BKx + bk) * 2048 + c];
        s.sl[c] = val;
        m = fmaxf(m, val);
    }
    float M = blockMax(m, s.red, tid);
    float sm = 0.f;
    for (int c = tid; c < Cx; c += 256) sm += expf(s.sl[c] - M);
    float S = blockSum(sm, s.red, tid);
    float lse = logf(S);
    float sc = g_score[bk];
    for (int c = tid; c < Cx; c += 256) {
        float lp = s.sl[c] - M - lse;
        out[((size_t)step * BKx + bk) * Cx + c] = lp;
        g_cand[(size_t)bk * Cx + c] = sc + lp;
    }
}

// ------------------------------ phase: top-k + gather -----------------------
__device__ void d_topk(int v, char* smemRaw) {
    SmemTopK& s = *reinterpret_cast<SmemTopK*>(smemRaw);
    const int b = v, tid = threadIdx.x;
    __syncthreads();

    for (int r = 0; r < 3; r++) {
        float bv = -INFINITY;
        int bi = 0x7fffffff;
        for (int j = tid; j < Kb * Cx; j += 256) {
            if (r > 0 && j == s.chI[0]) continue;
            if (r > 1 && j == s.chI[1]) continue;
            float val = g_cand[(size_t)(b * Kb + j / Cx) * Cx + (j % Cx)];
            if (val > bv || (val == bv && j < bi)) { bv = val; bi = j; }
        }
#pragma unroll
        for (int o = 16; o; o >>= 1) {
            float ov = __shfl_xor_sync(0xffffffffu, bv, o);
            int oi = __shfl_xor_sync(0xffffffffu, bi, o);
            if (ov > bv || (ov == bv && oi < bi)) { bv = ov; bi = oi; }
        }
        if ((tid & 31) == 0) { s.rv[tid >> 5] = bv; s.ri[tid >> 5] = bi; }
        __syncthreads();
        if (tid == 0) {
            float fv = s.rv[0]; int fi = s.ri[0];
#pragma unroll
            for (int w = 1; w < 8; w++) {
                if (s.rv[w] > fv || (s.rv[w] == fv && s.ri[w] < fi)) { fv = s.rv[w]; fi = s.ri[w]; }
            }
            s.chI[r] = fi; s.chV[r] = fv;
        }
        __syncthreads();
    }
    if (tid < 3) {
        int j = s.chI[tid];
        float val = s.chV[tid];
        int sym = j % Cx;
        g_inp[b * Kb + tid] = sym;
        g_score[b * Kb + tid] = (sym == EOSv) ? NEGV : val;
    }
    __syncthreads();

#pragma unroll
    for (int kb = 0; kb < 3; kb++) {
        int src = b * Kb + s.chI[kb] / Cx;
        int dstBk = b * Kb + kb;
#pragma unroll
        for (int l = 0; l < 2; l++) {
            size_t dst = ((size_t)l * BKx + dstBk) * Hx;
            size_t so  = ((size_t)l * BKx + src) * Hx;
#pragma unroll
            for (int j = 0; j < 4; j++) {
                int n = tid + j * 256;
                g_h[dst + n] = g_hs[so + n];
                g_c[dst + n] = g_cs[so + n];
            }
        }
    }
}

// ------------------------------ persistent decoder --------------------------
__global__ void __launch_bounds__(256)
decoder_kernel(int NB,
               const float* __restrict__ emb,
               const float* __restrict__ w_ih, const float* __restrict__ w_hh,
               const float* __restrict__ b_ih, const float* __restrict__ b_hh,
               const float* __restrict__ wq,   const float* __restrict__ bq,
               const float* __restrict__ ln1g, const float* __restrict__ ln1b,
               const float* __restrict__ wp,   const float* __restrict__ bp,
               const float* __restrict__ ln2g, const float* __restrict__ ln2b,
               const float* __restrict__ wg,   float* __restrict__ out) {
    __shared__ __align__(16) char SMEM[sizeof(SmemLstm)];
    unsigned gen = 0;
    const size_t WL = (size_t)4096 * Hx;

    for (int t = 0; t < Tx; t++) {
        for (int v = blockIdx.x; v < 16 * SPL; v += NB)
            d_gemm_lstm(v, SMEM, emb, g_inp, w_ih, g_h, w_hh, Hx / SPL, g_gatesP);
        gsync(NB, ++gen);
        d_point(NB, 0, b_ih, b_hh);
        gsync(NB, ++gen);
        for (int v = blockIdx.x; v < 16 * SPL; v += NB)
            d_gemm_lstm(v, SMEM, g_hs, nullptr, w_ih + WL, g_h + BKx * Hx, w_hh + WL,
                        Hx / SPL, g_gatesP);
        gsync(NB, ++gen);
        d_point(NB, 1, b_ih + 4096, b_hh + 4096);
        gsync(NB, ++gen);
        for (int v = blockIdx.x; v < 4 * SPQ; v += NB)
            d_gemm_kn(v, 2, SMEM, g_hs + BKx * Hx, wq, Hx / SPQ, Hx, Hx, g_qP);
        gsync(NB, ++gen);
        for (int v = blockIdx.x; v < 64; v += NB) d_attn(v, SMEM, bq);
        gsync(NB, ++gen);
        for (int v = blockIdx.x; v < 48; v += NB) d_ln1(v, SMEM, ln1g, ln1b);
        gsync(NB, ++gen);
        for (int v = blockIdx.x; v < 4 * SPQ; v += NB)
            d_gemm_kn(v, 2, SMEM, g_out1, wp, Hx / SPQ, Hx, Hx, g_pP);
        gsync(NB, ++gen);
        for (int v = blockIdx.x; v < 48; v += NB) d_ln2(v, SMEM, bp, ln2g, ln2b);
        gsync(NB, ++gen);
        for (int v = blockIdx.x; v < 8 * SPG; v += NB)
            d_gemm_kn(v, 3, SMEM, g_tanh, wg, Hx / SPG, Cx, 2048, g_gP);
        gsync(NB, ++gen);
        for (int v = blockIdx.x; v < 48; v += NB) d_lsm(v, SMEM, out, t);
        gsync(NB, ++gen);
        for (int v = blockIdx.x; v < Bb; v += NB) d_topk(v, SMEM);
        gsync(NB, ++gen);
    }
}

// ------------------------------ host launcher -------------------------------
extern "C" void kernel_launch(void* const* d_in, const int* in_sizes, int n_in,
                              void* d_out, int out_size) {
    const float* enc  = (const float*)d_in[0];
    const float* emb  = (const float*)d_in[1];
    const float* w_ih = (const float*)d_in[2];
    const float* w_hh = (const float*)d_in[3];
    const float* b_ih = (const float*)d_in[4];
    const float* b_hh = (const float*)d_in[5];
    const float* wq   = (const float*)d_in[6];
    const float* bq   = (const float*)d_in[7];
    const float* wk   = (const float*)d_in[8];
    const float* bk_  = (const float*)d_in[9];
    const float* wv   = (const float*)d_in[10];
    const float* bv   = (const float*)d_in[11];
    const float* ln1g = (const float*)d_in[12];
    const float* ln1b = (const float*)d_in[13];
    const float* wp   = (const float*)d_in[14];
    const float* bp   = (const float*)d_in[15];
    const float* ln2g = (const float*)d_in[16];
    const float* ln2b = (const float*)d_in[17];
    const float* wg   = (const float*)d_in[18];
    float* out = (float*)d_out;

    int dev = 0, sm = 148;
    cudaGetDevice(&dev);
    cudaDeviceGetAttribute(&sm, cudaDevAttrMultiProcessorCount, dev);
    int NB = sm;
    if (NB > 148) NB = 148;
    if (NB < 1) NB = 1;

    init_kernel<<<384, 256>>>();
    kvproj_kernel<<<dim3(8, 64), 256>>>(enc, wk, bk_, 0);
    kvproj_kernel<<<dim3(8, 64), 256>>>(enc, wv, bv, 1);
    decoder_kernel<<<NB, 256>>>(NB, emb, w_ih, w_hh, b_ih, b_hh, wq, bq,
                                ln1g, ln1b, wp, bp, ln2g, ln2b, wg, out);
    (void)in_sizes; (void)n_in; (void)out_size;
}

// round 10
// speedup vs baseline: 1.0900x; 1.0900x over previous
#include <cuda_runtime.h>
#include <math.h>
#include <stdint.h>
#include <stddef.h>

// ---------------------------------------------------------------------------
// SpeechTopKDecoder: T=64-step beam-search decoder. fp32 throughout.
// Deterministic: fixed-order split-K reductions, no float atomics.
// R10: launch-based (best base) + (1) attn unroll-16 (MLP/BW), (2) 512-thread
//      GEMM blocks 6x4 tiles (4 warps/SMSP), (3) single-pass top-3 + gather.
// ---------------------------------------------------------------------------

#define Bb   16
#define Kb   3
#define Sx   512
#define Hx   1024
#define Cx   2000
#define Tx   64
#define NHx  4
#define DHx  256
#define BKx  48
#define NEGV (-1000000000.0f)
#define SOSv 1
#define EOSv 2

#define SPL 8    // lstm split-K
#define SPQ 32   // q / p split-K
#define SPG 16   // wg split-K

// ------------------------------ device scratch ------------------------------
__device__ float g_kT [(size_t)Bb * NHx * DHx * Sx];   // keys   (B,NH,DH,S)
__device__ float g_vv [(size_t)Bb * NHx * Sx * DHx];   // values (B,NH,S,DH)
__device__ float g_h  [2 * BKx * Hx];
__device__ float g_c  [2 * BKx * Hx];
__device__ float g_hs [2 * BKx * Hx];
__device__ float g_cs [2 * BKx * Hx];
__device__ float g_gatesP[(size_t)SPL * BKx * 4096];
__device__ float g_qP [(size_t)SPQ * BKx * Hx];
__device__ float g_pP [(size_t)SPQ * BKx * Hx];
__device__ float g_gP [(size_t)SPG * BKx * 2048];
__device__ float g_ctx [BKx * Hx];
__device__ float g_out1[BKx * Hx];
__device__ float g_tanh[BKx * Hx];
__device__ float g_cand[BKx * Cx];
__device__ float g_score[BKx];
__device__ int   g_inp [BKx];

// ------------------------------ reductions ----------------------------------
__device__ __forceinline__ float warpMax(float v) {
#pragma unroll
    for (int o = 16; o; o >>= 1) v = fmaxf(v, __shfl_xor_sync(0xffffffffu, v, o));
    return v;
}
__device__ __forceinline__ float warpSum(float v) {
#pragma unroll
    for (int o = 16; o; o >>= 1) v += __shfl_xor_sync(0xffffffffu, v, o);
    return v;
}
__device__ __forceinline__ float blockMax(float v, float* red, int tid) {
    v = warpMax(v);
    if ((tid & 31) == 0) red[tid >> 5] = v;
    __syncthreads();
    float r = red[0];
#pragma unroll
    for (int w = 1; w < 8; w++) r = fmaxf(r, red[w]);
    __syncthreads();
    return r;
}
__device__ __forceinline__ float blockSum(float v, float* red, int tid) {
    v = warpSum(v);
    if ((tid & 31) == 0) red[tid >> 5] = v;
    __syncthreads();
    float r = red[0];
#pragma unroll
    for (int w = 1; w < 8; w++) r += red[w];
    __syncthreads();
    return r;
}
__device__ __forceinline__ float sigf(float x) { return 1.0f / (1.0f + expf(-x)); }

// ------------------------------ init ----------------------------------------
__global__ void init_kernel() {
    int idx = blockIdx.x * 256 + threadIdx.x;
    if (idx < 2 * BKx * Hx) { g_h[idx] = 0.0f; g_c[idx] = 0.0f; }
    if (idx < BKx) {
        g_score[idx] = (idx % Kb == 0) ? 0.0f : NEGV;
        g_inp[idx] = SOSv;
    }
}

// ------------------------------ K/V projection ------------------------------
// 128x128 tiles, 256 threads, 8x8 per thread. grid (8 n-tiles, 64 m-tiles).
__global__ void __launch_bounds__(256)
kvproj_kernel(const float* __restrict__ enc, const float* __restrict__ W,
              const float* __restrict__ bias, int z) {
    __shared__ float As[16][132];
    __shared__ float Bs[16][132];
    const int tid = threadIdx.x;
    const int tx = tid & 15, ty = tid >> 4;
    const int n0 = blockIdx.x * 128;
    const int m0 = blockIdx.y * 128;

    const int ak4 = tid & 3,  am = tid >> 2;
    const int bn4 = tid & 31, bkk = tid >> 5;

    float4 aR[2], bR[2];
    float acc[8][8];
#pragma unroll
    for (int i = 0; i < 8; i++)
#pragma unroll
        for (int j = 0; j < 8; j++) acc[i][j] = 0.0f;

#define KV_LOAD(kb)                                                            \
    {                                                                          \
        aR[0] = *(const float4*)(enc + (size_t)(m0 + am) * Hx + (kb) + ak4*4); \
        aR[1] = *(const float4*)(enc + (size_t)(m0 + 64 + am) * Hx + (kb) + ak4*4); \
        bR[0] = *(const float4*)(W + (size_t)((kb) + bkk) * Hx + n0 + bn4*4);  \
        bR[1] = *(const float4*)(W + (size_t)((kb) + 8 + bkk) * Hx + n0 + bn4*4); \
    }
#define KV_STORE()                                                             \
    {                                                                          \
        float av0[4] = {aR[0].x, aR[0].y, aR[0].z, aR[0].w};                   \
        float av1[4] = {aR[1].x, aR[1].y, aR[1].z, aR[1].w};                   \
        _Pragma("unroll")                                                      \
        for (int j = 0; j < 4; j++) {                                          \
            As[ak4*4 + j][am]      = av0[j];                                   \
            As[ak4*4 + j][64 + am] = av1[j];                                   \
        }                                                                      \
        *(float4*)&Bs[bkk][bn4*4]     = bR[0];                                 \
        *(float4*)&Bs[8 + bkk][bn4*4] = bR[1];                                 \
    }

    KV_LOAD(0);
#pragma unroll 1
    for (int t = 0; t < Hx / 16; t++) {
        __syncthreads();
        KV_STORE();
        __syncthreads();
        if (t + 1 < Hx / 16) KV_LOAD((t + 1) * 16);
#pragma unroll 2
        for (int kk = 0; kk < 16; kk++) {
            float a[8], b[8];
#pragma unroll
            for (int r = 0; r < 8; r++) a[r] = As[kk][ty + 16 * r];
#pragma unroll
            for (int k = 0; k < 8; k++) b[k] = Bs[kk][tx + 16 * k];
#pragma unroll
            for (int r = 0; r < 8; r++)
#pragma unroll
                for (int k = 0; k < 8; k++) acc[r][k] = fmaf(a[r], b[k], acc[r][k]);
        }
    }

#pragma unroll
    for (int r = 0; r < 8; r++) {
        int gm = m0 + ty + 16 * r;
        int b = gm >> 9, s = gm & 511;
#pragma unroll
        for (int k = 0; k < 8; k++) {
            int col = n0 + tx + 16 * k;
            int h = col >> 8, d = col & 255;
            float v = acc[r][k] + bias[col];
            if (z == 0)
                g_kT[(((size_t)b * NHx + h) * DHx + d) * Sx + s] = v;
            else
                g_vv[(((size_t)b * NHx + h) * Sx + s) * DHx + d] = v;
        }
    }
#undef KV_LOAD
#undef KV_STORE
}

// ------------------------------ LSTM GEMM (512 thr) -------------------------
// 48x256 tile, 512 threads, 6x4/thread. B is (N=4096, K=1024) row-major (two
// pairs). Bs n-major [256][33]. grid (16 n-tiles, SPL).
__global__ void __launch_bounds__(512)
gemm_lstm(const float* __restrict__ A0, const int* __restrict__ aidx,
          const float* __restrict__ B0,
          const float* __restrict__ A1, const float* __restrict__ B1,
          int kPerSplit, float* __restrict__ Cpart) {
    __shared__ float As[32][49];    // As[kk][m]
    __shared__ float Bs[256][33];   // Bs[n][kk]
    __shared__ int sIdx[48];

    const int tid = threadIdx.x;
    const int tx = tid & 63, ty = tid >> 6;   // tx: n-lane 0..63, ty: row-grp 0..7
    const int n0 = blockIdx.x * 256;
    const int sp = blockIdx.y;
    const int k0 = sp * kPerSplit;

    if (aidx != nullptr && tid < 48) sIdx[tid] = aidx[tid];

    const int bk4 = tid & 7;   // k-group 0..7
    const int bn  = tid >> 3;  // 0..63
    const int tilesPerPair = kPerSplit >> 5;
    const int ntiles = tilesPerPair * 2;

    float4 bR[4];
    float4 aR;
    float acc[6][4];
#pragma unroll
    for (int i = 0; i < 6; i++)
#pragma unroll
        for (int j = 0; j < 4; j++) acc[i][j] = 0.0f;

    __syncthreads();  // sIdx visible

#define LS_LOAD(t)                                                             \
    {                                                                          \
        int pair = (t) / tilesPerPair;                                         \
        int kb = k0 + ((t) - pair * tilesPerPair) * 32;                        \
        const float* A = pair ? A1 : A0;                                       \
        const float* B = pair ? B1 : B0;                                       \
        bool gat = (pair == 0) && (aidx != nullptr);                           \
        _Pragma("unroll")                                                      \
        for (int r = 0; r < 4; r++)                                            \
            bR[r] = *(const float4*)(B + (size_t)(n0 + bn + 64*r) * Hx + kb + bk4*4); \
        if (bn < 48) {                                                         \
            int r0 = gat ? sIdx[bn] : bn;                                      \
            aR = *(const float4*)(A + (size_t)r0 * Hx + kb + bk4*4);           \
        }                                                                      \
    }
#define LS_STORE()                                                             \
    {                                                                          \
        _Pragma("unroll")                                                      \
        for (int r = 0; r < 4; r++) {                                          \
            float bv[4] = {bR[r].x, bR[r].y, bR[r].z, bR[r].w};                \
            _Pragma("unroll")                                                  \
            for (int j = 0; j < 4; j++) Bs[bn + 64*r][bk4*4 + j] = bv[j];      \
        }                                                                      \
        if (bn < 48) {                                                         \
            float av[4] = {aR.x, aR.y, aR.z, aR.w};                            \
            _Pragma("unroll")                                                  \
            for (int j = 0; j < 4; j++) As[bk4*4 + j][bn] = av[j];             \
        }                                                                      \
    }

    LS_LOAD(0);
#pragma unroll 1
    for (int t = 0; t < ntiles; t++) {
        __syncthreads();
        LS_STORE();
        __syncthreads();
        if (t + 1 < ntiles) LS_LOAD(t + 1);
#pragma unroll 4
        for (int kk = 0; kk < 32; kk++) {
            float a[6];
#pragma unroll
            for (int r = 0; r < 6; r++) a[r] = As[kk][ty * 6 + r];
#pragma unroll
            for (int k = 0; k < 4; k++) {
                float b = Bs[tx + 64 * k][kk];
#pragma unroll
                for (int r = 0; r < 6; r++) acc[r][k] = fmaf(a[r], b, acc[r][k]);
            }
        }
    }

    float* Cb = Cpart + ((size_t)sp * 48 + ty * 6) * 4096 + n0 + tx;
#pragma unroll
    for (int r = 0; r < 6; r++)
#pragma unroll
        for (int k = 0; k < 4; k++) Cb[(size_t)r * 4096 + 64 * k] = acc[r][k];
#undef LS_LOAD
#undef LS_STORE
}

// ------------------------------ KN GEMM (512 thr) ---------------------------
// 48x256 tile, 512 threads, 6x4/thread. B is (K=1024, N) row-major.
// Bs kk-major [32][264]. grid (nTiles, split).
__global__ void __launch_bounds__(512)
gemm_kn(const float* __restrict__ A, const float* __restrict__ B,
        int kPerSplit, int Nreal, int Nstride, float* __restrict__ Cpart) {
    __shared__ float As[32][49];    // As[kk][m]
    __shared__ float Bs[32][264];   // Bs[kk][n]

    const int tid = threadIdx.x;
    const int tx = tid & 63, ty = tid >> 6;
    const int n0 = blockIdx.x * 256;
    const int sp = blockIdx.y;
    const int k0 = sp * kPerSplit;

    const int ak4 = tid & 7, am = tid >> 3;    // A loader (am<48 active)
    const int bn4 = tid & 63, bkk = tid >> 6;  // B loader: 4 reps, kk = bkk+8r

    const int ntiles = kPerSplit >> 5;

    float4 bR[4];
    float4 aR;
    float acc[6][4];
#pragma unroll
    for (int i = 0; i < 6; i++)
#pragma unroll
        for (int j = 0; j < 4; j++) acc[i][j] = 0.0f;

#define KN_LOAD(kb)                                                            \
    {                                                                          \
        int col = n0 + bn4 * 4;                                                \
        _Pragma("unroll")                                                      \
        for (int r = 0; r < 4; r++) {                                          \
            bR[r] = (col < Nreal)                                              \
                ? *(const float4*)(B + (size_t)((kb) + bkk + 8*r) * Nreal + col) \
                : make_float4(0.f, 0.f, 0.f, 0.f);                             \
        }                                                                      \
        if (am < 48)                                                           \
            aR = *(const float4*)(A + (size_t)am * Hx + (kb) + ak4*4);         \
    }
#define KN_STORE()                                                             \
    {                                                                          \
        _Pragma("unroll")                                                      \
        for (int r = 0; r < 4; r++) *(float4*)&Bs[bkk + 8*r][bn4*4] = bR[r];   \
        if (am < 48) {                                                         \
            float av[4] = {aR.x, aR.y, aR.z, aR.w};                            \
            _Pragma("unroll")                                                  \
            for (int j = 0; j < 4; j++) As[ak4*4 + j][am] = av[j];             \
        }                                                                      \
    }

    KN_LOAD(k0);
#pragma unroll 1
    for (int t = 0; t < ntiles; t++) {
        __syncthreads();
        KN_STORE();
        __syncthreads();
        if (t + 1 < ntiles) KN_LOAD(k0 + (t + 1) * 32);
#pragma unroll 4
        for (int kk = 0; kk < 32; kk++) {
            float a[6];
#pragma unroll
            for (int r = 0; r < 6; r++) a[r] = As[kk][ty * 6 + r];
#pragma unroll
            for (int k = 0; k < 4; k++) {
                float b = Bs[kk][tx + 64 * k];
#pragma unroll
                for (int r = 0; r < 6; r++) acc[r][k] = fmaf(a[r], b, acc[r][k]);
            }
        }
    }

    float* Cb = Cpart + ((size_t)sp * 48 + ty * 6) * Nstride + n0 + tx;
#pragma unroll
    for (int r = 0; r < 6; r++)
#pragma unroll
        for (int k = 0; k < 4; k++) Cb[(size_t)r * Nstride + 64 * k] = acc[r][k];
#undef KN_LOAD
#undef KN_STORE
}

// ------------------------------ LSTM pointwise ------------------------------
__global__ void lstm_point(int layer, const float* __restrict__ bih,
                           const float* __restrict__ bhh) {
    int idx = blockIdx.x * 256 + threadIdx.x;
    int bk = idx >> 10, n = idx & 1023;
    float iv = 0.f, fv = 0.f, gv = 0.f, ov = 0.f;
#pragma unroll
    for (int p = 0; p < SPL; p++) {
        const float* r = g_gatesP + ((size_t)p * BKx + bk) * 4096;
        iv += r[n]; fv += r[n + 1024]; gv += r[n + 2048]; ov += r[n + 3072];
    }
    iv += bih[n]        + bhh[n];
    fv += bih[n + 1024] + bhh[n + 1024];
    gv += bih[n + 2048] + bhh[n + 2048];
    ov += bih[n + 3072] + bhh[n + 3072];
    size_t off = ((size_t)layer * BKx + bk) * Hx + n;
    float cp = g_c[off];
    float cn = sigf(fv) * cp + sigf(iv) * tanhf(gv);
    float hn = sigf(ov) * tanhf(cn);
    g_cs[off] = cn;
    g_hs[off] = hn;
}

// ------------------------------ attention -----------------------------------
// unroll 16 on both streaming loops: 16 independent loads in flight per warp.
__global__ void attn_kernel(const float* __restrict__ bq) {
    const int b = blockIdx.x, h = blockIdx.y, tid = threadIdx.x;
    __shared__ float q[3][256];
    __shared__ float att[3][512];
    __shared__ float red[8];
    __shared__ float inv[3];

    for (int e = tid; e < 3 * 256; e += 256) {
        int kb = e >> 8, d = e & 255;
        int col = h * 256 + d, row = b * 3 + kb;
        float v = bq[col];
#pragma unroll
        for (int p = 0; p < SPQ; p++) v += g_qP[((size_t)p * BKx + row) * Hx + col];
        q[kb][d] = v;
    }
    __syncthreads();

    const float* kbase = g_kT + ((size_t)(b * NHx + h) * DHx) * Sx;
#pragma unroll
    for (int r = 0; r < 2; r++) {
        int s = tid + r * 256;
        float a0 = 0.f, a1 = 0.f, a2 = 0.f;
#pragma unroll 16
        for (int d = 0; d < 256; d++) {
            float kv = kbase[(size_t)d * Sx + s];
            a0 += q[0][d] * kv; a1 += q[1][d] * kv; a2 += q[2][d] * kv;
        }
        const float sc = 1.0f / 16.0f;
        att[0][s] = a0 * sc; att[1][s] = a1 * sc; att[2][s] = a2 * sc;
    }
    __syncthreads();

#pragma unroll
    for (int kb = 0; kb < 3; kb++) {
        float m = fmaxf(att[kb][tid], att[kb][tid + 256]);
        m = blockMax(m, red, tid);
        float e0 = expf(att[kb][tid] - m);
        float e1 = expf(att[kb][tid + 256] - m);
        att[kb][tid] = e0; att[kb][tid + 256] = e1;
        __syncthreads();
        float s = blockSum(e0 + e1, red, tid);
        if (tid == 0) inv[kb] = 1.0f / s;
    }
    __syncthreads();

    const int d = tid;
    const float* vbase = g_vv + ((size_t)(b * NHx + h) * Sx) * DHx + d;
    float c0 = 0.f, c1 = 0.f, c2 = 0.f;
#pragma unroll 16
    for (int s = 0; s < Sx; s++) {
        float v = vbase[(size_t)s * DHx];
        c0 += att[0][s] * v; c1 += att[1][s] * v; c2 += att[2][s] * v;
    }
    g_ctx[(size_t)(b * 3 + 0) * Hx + h * 256 + d] = c0 * inv[0];
    g_ctx[(size_t)(b * 3 + 1) * Hx + h * 256 + d] = c1 * inv[1];
    g_ctx[(size_t)(b * 3 + 2) * Hx + h * 256 + d] = c2 * inv[2];
}

// ------------------------------ layernorms ----------------------------------
__global__ void ln1_kernel(const float* __restrict__ g1, const float* __restrict__ b1) {
    const int bk = blockIdx.x, tid = threadIdx.x;
    __shared__ float y[Hx];
    __shared__ float red[8];
    float loc = 0.f;
#pragma unroll
    for (int j = 0; j < 4; j++) {
        int n = tid + j * 256;
        float v = g_ctx[(size_t)bk * Hx + n] + g_hs[((size_t)1 * BKx + bk) * Hx + n];
        y[n] = v; loc += v;
    }
    float mean = blockSum(loc, red, tid) * (1.0f / Hx);
    float loc2 = 0.f;
#pragma unroll
    for (int j = 0; j < 4; j++) {
        int n = tid + j * 256;
        float d = y[n] - mean; loc2 += d * d;
    }
    float var = blockSum(loc2, red, tid) * (1.0f / Hx);
    float w = rsqrtf(var + 1e-5f);
#pragma unroll
    for (int j = 0; j < 4; j++) {
        int n = tid + j * 256;
        g_out1[(size_t)bk * Hx + n] = (y[n] - mean) * w * g1[n] + b1[n];
    }
}

__global__ void ln2tanh_kernel(const float* __restrict__ bp,
                               const float* __restrict__ g2, const float* __restrict__ b2) {
    const int bk = blockIdx.x, tid = threadIdx.x;
    __shared__ float y[Hx];
    __shared__ float red[8];
    float loc = 0.f;
#pragma unroll
    for (int j = 0; j < 4; j++) {
        int n = tid + j * 256;
        float v = bp[n] + g_out1[(size_t)bk * Hx + n];
#pragma unroll
        for (int p = 0; p < SPQ; p++) v += g_pP[((size_t)p * BKx + bk) * Hx + n];
        y[n] = v; loc += v;
    }
    float mean = blockSum(loc, red, tid) * (1.0f / Hx);
    float loc2 = 0.f;
#pragma unroll
    for (int j = 0; j < 4; j++) {
        int n = tid + j * 256;
        float d = y[n] - mean; loc2 += d * d;
    }
    float var = blockSum(loc2, red, tid) * (1.0f / Hx);
    float w = rsqrtf(var + 1e-5f);
#pragma unroll
    for (int j = 0; j < 4; j++) {
        int n = tid + j * 256;
        g_tanh[(size_t)bk * Hx + n] = tanhf((y[n] - mean) * w * g2[n] + b2[n]);
    }
}

// ------------------------------ log-softmax + output ------------------------
__global__ void lsm_kernel(float* __restrict__ out, int step) {
    const int bk = blockIdx.x, tid = threadIdx.x;
    __shared__ float sl[Cx];
    __shared__ float red[8];
    float m = -INFINITY;
    for (int c = tid; c < Cx; c += 256) {
        float v = 0.f;
#pragma unroll
        for (int p = 0; p < SPG; p++) v += g_gP[((size_t)p * BKx + bk) * 2048 + c];
        sl[c] = v;
        m = fmaxf(m, v);
    }
    float M = blockMax(m, red, tid);
    float s = 0.f;
    for (int c = tid; c < Cx; c += 256) s += expf(sl[c] - M);
    float S = blockSum(s, red, tid);
    float lse = logf(S);
    float sc = g_score[bk];
    for (int c = tid; c < Cx; c += 256) {
        float lp = sl[c] - M - lse;
        out[((size_t)step * BKx + bk) * Cx + c] = lp;
        g_cand[(size_t)bk * Cx + c] = sc + lp;
    }
}

// ---------------- single-pass top-3 + beam update + gather ------------------
// Strict total order (value desc, index asc) == lax.top_k semantics (keys
// unique by index). Selection of 3 maxima under a strict total order is
// merge-order-independent, so per-thread lists + shuffles are exact.
__device__ __forceinline__ void ins3(float v, int j,
                                     float& v0, int& j0, float& v1, int& j1,
                                     float& v2, int& j2) {
    if (v > v0 || (v == v0 && j < j0)) {
        v2 = v1; j2 = j1; v1 = v0; j1 = j0; v0 = v; j0 = j;
    } else if (v > v1 || (v == v1 && j < j1)) {
        v2 = v1; j2 = j1; v1 = v; j1 = j;
    } else if (v > v2 || (v == v2 && j < j2)) {
        v2 = v; j2 = j;
    }
}

__global__ void topk_gather_kernel() {
    const int b = blockIdx.x, tid = threadIdx.x;
    __shared__ float sv[8][3];
    __shared__ int si[8][3];
    __shared__ int chI[3];
    __shared__ float chV[3];

    float v0 = -INFINITY, v1 = -INFINITY, v2 = -INFINITY;
    int j0 = 0x7fffffff, j1 = 0x7fffffff, j2 = 0x7fffffff;
    for (int j = tid; j < Kb * Cx; j += 256) {
        float v = g_cand[(size_t)(b * Kb + j / Cx) * Cx + (j % Cx)];
        ins3(v, j, v0, j0, v1, j1, v2, j2);
    }
#pragma unroll
    for (int o = 16; o; o >>= 1) {
        float w0 = __shfl_xor_sync(0xffffffffu, v0, o);
        float w1 = __shfl_xor_sync(0xffffffffu, v1, o);
        float w2 = __shfl_xor_sync(0xffffffffu, v2, o);
        int k0 = __shfl_xor_sync(0xffffffffu, j0, o);
        int k1 = __shfl_xor_sync(0xffffffffu, j1, o);
        int k2 = __shfl_xor_sync(0xffffffffu, j2, o);
        ins3(w0, k0, v0, j0, v1, j1, v2, j2);
        ins3(w1, k1, v0, j0, v1, j1, v2, j2);
        ins3(w2, k2, v0, j0, v1, j1, v2, j2);
    }
    if ((tid & 31) == 0) {
        int w = tid >> 5;
        sv[w][0] = v0; sv[w][1] = v1; sv[w][2] = v2;
        si[w][0] = j0; si[w][1] = j1; si[w][2] = j2;
    }
    __syncthreads();
    if (tid == 0) {
        float f0 = -INFINITY, f1 = -INFINITY, f2 = -INFINITY;
        int g0 = 0x7fffffff, g1 = 0x7fffffff, g2 = 0x7fffffff;
#pragma unroll
        for (int w = 0; w < 8; w++)
#pragma unroll
            for (int e = 0; e < 3; e++)
                ins3(sv[w][e], si[w][e], f0, g0, f1, g1, f2, g2);
        chI[0] = g0; chV[0] = f0;
        chI[1] = g1; chV[1] = f1;
        chI[2] = g2; chV[2] = f2;
    }
    __syncthreads();

    if (tid < 3) {
        int j = chI[tid];
        float v = chV[tid];
        int sym = j % Cx;
        g_inp[b * Kb + tid] = sym;
        g_score[b * Kb + tid] = (sym == EOSv) ? NEGV : v;
    }
    __syncthreads();

    // gather h/c (beam sources are intra-batch: block-local, safe)
#pragma unroll
    for (int kb = 0; kb < 3; kb++) {
        int src = b * Kb + chI[kb] / Cx;
        int dstBk = b * Kb + kb;
#pragma unroll
        for (int l = 0; l < 2; l++) {
            size_t dst = ((size_t)l * BKx + dstBk) * Hx;
            size_t so  = ((size_t)l * BKx + src) * Hx;
#pragma unroll
            for (int j = 0; j < 4; j++) {
                int n = tid + j * 256;
                g_h[dst + n] = g_hs[so + n];
                g_c[dst + n] = g_cs[so + n];
            }
        }
    }
}

// ------------------------------ host launcher -------------------------------
extern "C" void kernel_launch(void* const* d_in, const int* in_sizes, int n_in,
                              void* d_out, int out_size) {
    const float* enc  = (const float*)d_in[0];
    const float* emb  = (const float*)d_in[1];
    const float* w_ih = (const float*)d_in[2];
    const float* w_hh = (const float*)d_in[3];
    const float* b_ih = (const float*)d_in[4];
    const float* b_hh = (const float*)d_in[5];
    const float* wq   = (const float*)d_in[6];
    const float* bq   = (const float*)d_in[7];
    const float* wk   = (const float*)d_in[8];
    const float* bk_  = (const float*)d_in[9];
    const float* wv   = (const float*)d_in[10];
    const float* bv   = (const float*)d_in[11];
    const float* ln1g = (const float*)d_in[12];
    const float* ln1b = (const float*)d_in[13];
    const float* wp   = (const float*)d_in[14];
    const float* bp   = (const float*)d_in[15];
    const float* ln2g = (const float*)d_in[16];
    const float* ln2b = (const float*)d_in[17];
    const float* wg   = (const float*)d_in[18];
    float* out = (float*)d_out;

    float *p_h, *p_hs, *p_out1, *p_tanh, *p_gatesP, *p_qP, *p_pP, *p_gP;
    int* p_inp;
    cudaGetSymbolAddress((void**)&p_h, g_h);
    cudaGetSymbolAddress((void**)&p_hs, g_hs);
    cudaGetSymbolAddress((void**)&p_out1, g_out1);
    cudaGetSymbolAddress((void**)&p_tanh, g_tanh);
    cudaGetSymbolAddress((void**)&p_gatesP, g_gatesP);
    cudaGetSymbolAddress((void**)&p_qP, g_qP);
    cudaGetSymbolAddress((void**)&p_pP, g_pP);
    cudaGetSymbolAddress((void**)&p_gP, g_gP);
    cudaGetSymbolAddress((void**)&p_inp, g_inp);

    init_kernel<<<384, 256>>>();
    // two launches so ncu -s 5 -c 1 lands on gemm_lstm
    kvproj_kernel<<<dim3(8, 64), 256>>>(enc, wk, bk_, 0);
    kvproj_kernel<<<dim3(8, 64), 256>>>(enc, wv, bv, 1);

    const size_t WL = (size_t)4096 * Hx;

    for (int t = 0; t < Tx; t++) {
        gemm_lstm<<<dim3(16, SPL), 512>>>(emb, p_inp, w_ih,
                                          p_h, w_hh, Hx / SPL, p_gatesP);
        lstm_point<<<192, 256>>>(0, b_ih, b_hh);
        gemm_lstm<<<dim3(16, SPL), 512>>>(p_hs, nullptr, w_ih + WL,
                                          p_h + BKx * Hx, w_hh + WL,
                                          Hx / SPL, p_gatesP);
        lstm_point<<<192, 256>>>(1, b_ih + 4096, b_hh + 4096);
        gemm_kn<<<dim3(4, SPQ), 512>>>(p_hs + BKx * Hx, wq, Hx / SPQ, Hx, Hx, p_qP);
        attn_kernel<<<dim3(16, 4), 256>>>(bq);
        ln1_kernel<<<48, 256>>>(ln1g, ln1b);
        gemm_kn<<<dim3(4, SPQ), 512>>>(p_out1, wp, Hx / SPQ, Hx, Hx, p_pP);
        ln2tanh_kernel<<<48, 256>>>(bp, ln2g, ln2b);
        gemm_kn<<<dim3(8, SPG), 512>>>(p_tanh, wg, Hx / SPG, Cx, 2048, p_gP);
        lsm_kernel<<<48, 256>>>(out, t);
        topk_gather_kernel<<<16, 256>>>();
    }
    (void)in_sizes; (void)n_in; (void)out_size;
}

// round 13
// speedup vs baseline: 1.1264x; 1.0334x over previous
#include <cuda_runtime.h>
#include <math.h>
#include <stdint.h>
#include <stddef.h>

// ---------------------------------------------------------------------------
// SpeechTopKDecoder: T=64-step beam-search decoder. fp32 throughout.
// Deterministic: fixed-order split-K reductions, no float atomics.
// R13 (third submit of the best-of-each build; prior two rounds died to
// broker/container failures before the kernel ever ran):
//   - R4 GEMM micro-kernels (256 threads, 6x8 thread tiles, reg double-buffer)
//   - R10 attention with unroll-16 streaming loops (MLP ~16/warp)
//   - R10 single-pass top-3 (strict total order == lax.top_k) + fused gather
// ---------------------------------------------------------------------------

#define Bb   16
#define Kb   3
#define Sx   512
#define Hx   1024
#define Cx   2000
#define Tx   64
#define NHx  4
#define DHx  256
#define BKx  48
#define NEGV (-1000000000.0f)
#define SOSv 1
#define EOSv 2

#define SPL 8    // lstm split-K
#define SPQ 32   // q / p split-K
#define SPG 16   // wg split-K

// ------------------------------ device scratch ------------------------------
__device__ float g_kT [(size_t)Bb * NHx * DHx * Sx];   // keys   (B,NH,DH,S)
__device__ float g_vv [(size_t)Bb * NHx * Sx * DHx];   // values (B,NH,S,DH)
__device__ float g_h  [2 * BKx * Hx];
__device__ float g_c  [2 * BKx * Hx];
__device__ float g_hs [2 * BKx * Hx];
__device__ float g_cs [2 * BKx * Hx];
__device__ float g_gatesP[(size_t)SPL * BKx * 4096];
__device__ float g_qP [(size_t)SPQ * BKx * Hx];
__device__ float g_pP [(size_t)SPQ * BKx * Hx];
__device__ float g_gP [(size_t)SPG * BKx * 2048];
__device__ float g_ctx [BKx * Hx];
__device__ float g_out1[BKx * Hx];
__device__ float g_tanh[BKx * Hx];
__device__ float g_cand[BKx * Cx];
__device__ float g_score[BKx];
__device__ int   g_inp [BKx];

// ------------------------------ reductions ----------------------------------
__device__ __forceinline__ float warpMax(float v) {
#pragma unroll
    for (int o = 16; o; o >>= 1) v = fmaxf(v, __shfl_xor_sync(0xffffffffu, v, o));
    return v;
}
__device__ __forceinline__ float warpSum(float v) {
#pragma unroll
    for (int o = 16; o; o >>= 1) v += __shfl_xor_sync(0xffffffffu, v, o);
    return v;
}
__device__ __forceinline__ float blockMax(float v, float* red, int tid) {
    v = warpMax(v);
    if ((tid & 31) == 0) red[tid >> 5] = v;
    __syncthreads();
    float r = red[0];
#pragma unroll
    for (int w = 1; w < 8; w++) r = fmaxf(r, red[w]);
    __syncthreads();
    return r;
}
__device__ __forceinline__ float blockSum(float v, float* red, int tid) {
    v = warpSum(v);
    if ((tid & 31) == 0) red[tid >> 5] = v;
    __syncthreads();
    float r = red[0];
#pragma unroll
    for (int w = 1; w < 8; w++) r += red[w];
    __syncthreads();
    return r;
}
__device__ __forceinline__ float sigf(float x) { return 1.0f / (1.0f + expf(-x)); }

// ------------------------------ init ----------------------------------------
__global__ void init_kernel() {
    int idx = blockIdx.x * 256 + threadIdx.x;
    if (idx < 2 * BKx * Hx) { g_h[idx] = 0.0f; g_c[idx] = 0.0f; }
    if (idx < BKx) {
        g_score[idx] = (idx % Kb == 0) ? 0.0f : NEGV;
        g_inp[idx] = SOSv;
    }
}

// ------------------------------ K/V projection ------------------------------
// One-time: enc(8192,1024) x W(1024,1024). 128x128 tiles, 256 threads,
// 8x8 per thread. grid (8 n-tiles, 64 m-tiles). K stored transposed for attn.
__global__ void __launch_bounds__(256)
kvproj_kernel(const float* __restrict__ enc, const float* __restrict__ W,
              const float* __restrict__ bias, int z) {
    __shared__ float As[16][132];
    __shared__ float Bs[16][132];
    const int tid = threadIdx.x;
    const int tx = tid & 15, ty = tid >> 4;
    const int n0 = blockIdx.x * 128;
    const int m0 = blockIdx.y * 128;

    const int ak4 = tid & 3,  am = tid >> 2;
    const int bn4 = tid & 31, bkk = tid >> 5;

    float4 aR[2], bR[2];
    float acc[8][8];
#pragma unroll
    for (int i = 0; i < 8; i++)
#pragma unroll
        for (int j = 0; j < 8; j++) acc[i][j] = 0.0f;

#define KV_LOAD(kb)                                                            \
    {                                                                          \
        aR[0] = *(const float4*)(enc + (size_t)(m0 + am) * Hx + (kb) + ak4*4); \
        aR[1] = *(const float4*)(enc + (size_t)(m0 + 64 + am) * Hx + (kb) + ak4*4); \
        bR[0] = *(const float4*)(W + (size_t)((kb) + bkk) * Hx + n0 + bn4*4);  \
        bR[1] = *(const float4*)(W + (size_t)((kb) + 8 + bkk) * Hx + n0 + bn4*4); \
    }
#define KV_STORE()                                                             \
    {                                                                          \
        float av0[4] = {aR[0].x, aR[0].y, aR[0].z, aR[0].w};                   \
        float av1[4] = {aR[1].x, aR[1].y, aR[1].z, aR[1].w};                   \
        _Pragma("unroll")                                                      \
        for (int j = 0; j < 4; j++) {                                          \
            As[ak4*4 + j][am]      = av0[j];                                   \
            As[ak4*4 + j][64 + am] = av1[j];                                   \
        }                                                                      \
        *(float4*)&Bs[bkk][bn4*4]     = bR[0];                                 \
        *(float4*)&Bs[8 + bkk][bn4*4] = bR[1];                                 \
    }

    KV_LOAD(0);
#pragma unroll 1
    for (int t = 0; t < Hx / 16; t++) {
        __syncthreads();
        KV_STORE();
        __syncthreads();
        if (t + 1 < Hx / 16) KV_LOAD((t + 1) * 16);
#pragma unroll 2
        for (int kk = 0; kk < 16; kk++) {
            float a[8], b[8];
#pragma unroll
            for (int r = 0; r < 8; r++) a[r] = As[kk][ty + 16 * r];
#pragma unroll
            for (int k = 0; k < 8; k++) b[k] = Bs[kk][tx + 16 * k];
#pragma unroll
            for (int r = 0; r < 8; r++)
#pragma unroll
                for (int k = 0; k < 8; k++) acc[r][k] = fmaf(a[r], b[k], acc[r][k]);
        }
    }

#pragma unroll
    for (int r = 0; r < 8; r++) {
        int gm = m0 + ty + 16 * r;
        int b = gm >> 9, s = gm & 511;
#pragma unroll
        for (int k = 0; k < 8; k++) {
            int col = n0 + tx + 16 * k;
            int h = col >> 8, d = col & 255;
            float v = acc[r][k] + bias[col];
            if (z == 0)
                g_kT[(((size_t)b * NHx + h) * DHx + d) * Sx + s] = v;
            else
                g_vv[(((size_t)b * NHx + h) * Sx + s) * DHx + d] = v;
        }
    }
#undef KV_LOAD
#undef KV_STORE
}

// ------------------------------ LSTM GEMM -----------------------------------
// Measured-best config: 48x256 tile, 256 threads, 6x8 per thread.
// B is (N=4096, K=1024) row-major, two pairs (w_ih then w_hh). Bs stored
// n-major [256][33] (transpose-free from NK layout). grid (16 n-tiles, SPL).
__global__ void __launch_bounds__(256)
gemm_lstm(const float* __restrict__ A0, const int* __restrict__ aidx,
          const float* __restrict__ B0,
          const float* __restrict__ A1, const float* __restrict__ B1,
          int kPerSplit, float* __restrict__ Cpart) {
    __shared__ float As[32][49];    // As[kk][m]
    __shared__ float Bs[256][33];   // Bs[n][kk]
    __shared__ int sIdx[48];

    const int tid = threadIdx.x;
    const int tx = tid & 31, ty = tid >> 5;
    const int n0 = blockIdx.x * 256;
    const int sp = blockIdx.y;
    const int k0 = sp * kPerSplit;

    if (aidx != nullptr && tid < 48) sIdx[tid] = aidx[tid];

    const int bk4 = tid & 7;   // k-group 0..7
    const int bn  = tid >> 3;  // 0..31

    const int tilesPerPair = kPerSplit >> 5;
    const int ntiles = tilesPerPair * 2;

    float4 bR[8];
    float4 aR[2];
    float acc[6][8];
#pragma unroll
    for (int i = 0; i < 6; i++)
#pragma unroll
        for (int j = 0; j < 8; j++) acc[i][j] = 0.0f;

    __syncthreads();  // sIdx visible

#define LS_LOAD(t)                                                             \
    {                                                                          \
        int pair = (t) / tilesPerPair;                                         \
        int kb = k0 + ((t) - pair * tilesPerPair) * 32;                        \
        const float* A = pair ? A1 : A0;                                       \
        const float* B = pair ? B1 : B0;                                       \
        bool gat = (pair == 0) && (aidx != nullptr);                           \
        _Pragma("unroll")                                                      \
        for (int r = 0; r < 8; r++)                                            \
            bR[r] = *(const float4*)(B + (size_t)(n0 + bn + 32*r) * Hx + kb + bk4*4); \
        int r0 = gat ? sIdx[bn] : bn;                                          \
        aR[0] = *(const float4*)(A + (size_t)r0 * Hx + kb + bk4*4);            \
        if (bn < 16) {                                                         \
            int r1 = gat ? sIdx[32 + bn] : (32 + bn);                          \
            aR[1] = *(const float4*)(A + (size_t)r1 * Hx + kb + bk4*4);        \
        }                                                                      \
    }
#define LS_STORE()                                                             \
    {                                                                          \
        _Pragma("unroll")                                                      \
        for (int r = 0; r < 8; r++) {                                          \
            float bv[4] = {bR[r].x, bR[r].y, bR[r].z, bR[r].w};                \
            _Pragma("unroll")                                                  \
            for (int j = 0; j < 4; j++) Bs[bn + 32*r][bk4*4 + j] = bv[j];      \
        }                                                                      \
        float av0[4] = {aR[0].x, aR[0].y, aR[0].z, aR[0].w};                   \
        _Pragma("unroll")                                                      \
        for (int j = 0; j < 4; j++) As[bk4*4 + j][bn] = av0[j];                \
        if (bn < 16) {                                                         \
            float av1[4] = {aR[1].x, aR[1].y, aR[1].z, aR[1].w};               \
            _Pragma("unroll")                                                  \
            for (int j = 0; j < 4; j++) As[bk4*4 + j][32 + bn] = av1[j];       \
        }                                                                      \
    }

    LS_LOAD(0);
#pragma unroll 1
    for (int t = 0; t < ntiles; t++) {
        __syncthreads();
        LS_STORE();
        __syncthreads();
        if (t + 1 < ntiles) LS_LOAD(t + 1);
#pragma unroll 4
        for (int kk = 0; kk < 32; kk++) {
            float a[6];
#pragma unroll
            for (int r = 0; r < 6; r++) a[r] = As[kk][ty * 6 + r];
#pragma unroll
            for (int k = 0; k < 8; k++) {
                float b = Bs[tx + 32 * k][kk];
#pragma unroll
                for (int r = 0; r < 6; r++) acc[r][k] = fmaf(a[r], b, acc[r][k]);
            }
        }
    }

    float* Cb = Cpart + ((size_t)sp * 48 + ty * 6) * 4096 + n0 + tx;
#pragma unroll
    for (int r = 0; r < 6; r++)
#pragma unroll
        for (int k = 0; k < 8; k++) Cb[(size_t)r * 4096 + 32 * k] = acc[r][k];
#undef LS_LOAD
#undef LS_STORE
}

// ------------------------------ KN GEMM (q/p/wg) ----------------------------
// Measured-best config: 48x256 tile, 256 threads, 6x8 per thread.
// B is (K=1024, N) row-major. Bs stored kk-major [32][264]; full-tile loader.
__global__ void __launch_bounds__(256)
gemm_kn(const float* __restrict__ A, const float* __restrict__ B,
        int kPerSplit, int Nreal, int Nstride, float* __restrict__ Cpart) {
    __shared__ float As[32][49];    // As[kk][m]
    __shared__ float Bs[32][264];   // Bs[kk][n]

    const int tid = threadIdx.x;
    const int tx = tid & 31, ty = tid >> 5;
    const int n0 = blockIdx.x * 256;
    const int sp = blockIdx.y;
    const int k0 = sp * kPerSplit;

    const int ak4 = tid & 7, am = tid >> 3;    // A loader
    const int bn4 = tid & 63, bkk = tid >> 6;  // B loader: 8 reps, kk = bkk+4r

    const int ntiles = kPerSplit >> 5;

    float4 bR[8];
    float4 aR[2];
    float acc[6][8];
#pragma unroll
    for (int i = 0; i < 6; i++)
#pragma unroll
        for (int j = 0; j < 8; j++) acc[i][j] = 0.0f;

#define KN_LOAD(kb)                                                            \
    {                                                                          \
        int col = n0 + bn4 * 4;                                                \
        _Pragma("unroll")                                                      \
        for (int r = 0; r < 8; r++) {                                          \
            bR[r] = (col < Nreal)                                              \
                ? *(const float4*)(B + (size_t)((kb) + bkk + 4*r) * Nreal + col) \
                : make_float4(0.f, 0.f, 0.f, 0.f);                             \
        }                                                                      \
        aR[0] = *(const float4*)(A + (size_t)am * Hx + (kb) + ak4*4);          \
        if (am < 16)                                                           \
            aR[1] = *(const float4*)(A + (size_t)(32 + am) * Hx + (kb) + ak4*4); \
    }
#define KN_STORE()                                                             \
    {                                                                          \
        _Pragma("unroll")                                                      \
        for (int r = 0; r < 8; r++) *(float4*)&Bs[bkk + 4*r][bn4*4] = bR[r];   \
        float av0[4] = {aR[0].x, aR[0].y, aR[0].z, aR[0].w};                   \
        _Pragma("unroll")                                                      \
        for (int j = 0; j < 4; j++) As[ak4*4 + j][am] = av0[j];                \
        if (am < 16) {                                                         \
            float av1[4] = {aR[1].x, aR[1].y, aR[1].z, aR[1].w};               \
            _Pragma("unroll")                                                  \
            for (int j = 0; j < 4; j++) As[ak4*4 + j][32 + am] = av1[j];       \
        }                                                                      \
    }

    KN_LOAD(k0);
#pragma unroll 1
    for (int t = 0; t < ntiles; t++) {
        __syncthreads();
        KN_STORE();
        __syncthreads();
        if (t + 1 < ntiles) KN_LOAD(k0 + (t + 1) * 32);
#pragma unroll 4
        for (int kk = 0; kk < 32; kk++) {
            float a[6];
#pragma unroll
            for (int r = 0; r < 6; r++) a[r] = As[kk][ty * 6 + r];
#pragma unroll
            for (int k = 0; k < 8; k++) {
                float b = Bs[kk][tx + 32 * k];
#pragma unroll
                for (int r = 0; r < 6; r++) acc[r][k] = fmaf(a[r], b, acc[r][k]);
            }
        }
    }

    float* Cb = Cpart + ((size_t)sp * 48 + ty * 6) * Nstride + n0 + tx;
#pragma unroll
    for (int r = 0; r < 6; r++)
#pragma unroll
        for (int k = 0; k < 8; k++) Cb[(size_t)r * Nstride + 32 * k] = acc[r][k];
#undef KN_LOAD
#undef KN_STORE
}

// ------------------------------ LSTM pointwise ------------------------------
__global__ void lstm_point(int layer, const float* __restrict__ bih,
                           const float* __restrict__ bhh) {
    int idx = blockIdx.x * 256 + threadIdx.x;
    int bk = idx >> 10, n = idx & 1023;
    float iv = 0.f, fv = 0.f, gv = 0.f, ov = 0.f;
#pragma unroll
    for (int p = 0; p < SPL; p++) {
        const float* r = g_gatesP + ((size_t)p * BKx + bk) * 4096;
        iv += r[n]; fv += r[n + 1024]; gv += r[n + 2048]; ov += r[n + 3072];
    }
    iv += bih[n]        + bhh[n];
    fv += bih[n + 1024] + bhh[n + 1024];
    gv += bih[n + 2048] + bhh[n + 2048];
    ov += bih[n + 3072] + bhh[n + 3072];
    size_t off = ((size_t)layer * BKx + bk) * Hx + n;
    float cp = g_c[off];
    float cn = sigf(fv) * cp + sigf(iv) * tanhf(gv);
    float hn = sigf(ov) * tanhf(cn);
    g_cs[off] = cn;
    g_hs[off] = hn;
}

// ------------------------------ attention -----------------------------------
// Streaming loops unrolled 16-deep: ~16 independent loads in flight per warp
// over the 1 MB K+V working set of each (batch, head) block.
__global__ void attn_kernel(const float* __restrict__ bq) {
    const int b = blockIdx.x, h = blockIdx.y, tid = threadIdx.x;
    __shared__ float q[3][256];
    __shared__ float att[3][512];
    __shared__ float red[8];
    __shared__ float inv[3];

    for (int e = tid; e < 3 * 256; e += 256) {
        int kb = e >> 8, d = e & 255;
        int col = h * 256 + d, row = b * 3 + kb;
        float v = bq[col];
#pragma unroll
        for (int p = 0; p < SPQ; p++) v += g_qP[((size_t)p * BKx + row) * Hx + col];
        q[kb][d] = v;
    }
    __syncthreads();

    const float* kbase = g_kT + ((size_t)(b * NHx + h) * DHx) * Sx;
#pragma unroll
    for (int r = 0; r < 2; r++) {
        int s = tid + r * 256;
        float a0 = 0.f, a1 = 0.f, a2 = 0.f;
#pragma unroll 16
        for (int d = 0; d < 256; d++) {
            float kv = kbase[(size_t)d * Sx + s];
            a0 += q[0][d] * kv; a1 += q[1][d] * kv; a2 += q[2][d] * kv;
        }
        const float sc = 1.0f / 16.0f;  // 1/sqrt(DH)
        att[0][s] = a0 * sc; att[1][s] = a1 * sc; att[2][s] = a2 * sc;
    }
    __syncthreads();

#pragma unroll
    for (int kb = 0; kb < 3; kb++) {
        float m = fmaxf(att[kb][tid], att[kb][tid + 256]);
        m = blockMax(m, red, tid);
        float e0 = expf(att[kb][tid] - m);
        float e1 = expf(att[kb][tid + 256] - m);
        att[kb][tid] = e0; att[kb][tid + 256] = e1;
        __syncthreads();
        float s = blockSum(e0 + e1, red, tid);
        if (tid == 0) inv[kb] = 1.0f / s;
    }
    __syncthreads();

    const int d = tid;
    const float* vbase = g_vv + ((size_t)(b * NHx + h) * Sx) * DHx + d;
    float c0 = 0.f, c1 = 0.f, c2 = 0.f;
#pragma unroll 16
    for (int s = 0; s < Sx; s++) {
        float v = vbase[(size_t)s * DHx];
        c0 += att[0][s] * v; c1 += att[1][s] * v; c2 += att[2][s] * v;
    }
    g_ctx[(size_t)(b * 3 + 0) * Hx + h * 256 + d] = c0 * inv[0];
    g_ctx[(size_t)(b * 3 + 1) * Hx + h * 256 + d] = c1 * inv[1];
    g_ctx[(size_t)(b * 3 + 2) * Hx + h * 256 + d] = c2 * inv[2];
}

// ------------------------------ layernorms ----------------------------------
__global__ void ln1_kernel(const float* __restrict__ g1, const float* __restrict__ b1) {
    const int bk = blockIdx.x, tid = threadIdx.x;
    __shared__ float y[Hx];
    __shared__ float red[8];
    float loc = 0.f;
#pragma unroll
    for (int j = 0; j < 4; j++) {
        int n = tid + j * 256;
        float v = g_ctx[(size_t)bk * Hx + n] + g_hs[((size_t)1 * BKx + bk) * Hx + n];
        y[n] = v; loc += v;
    }
    float mean = blockSum(loc, red, tid) * (1.0f / Hx);
    float loc2 = 0.f;
#pragma unroll
    for (int j = 0; j < 4; j++) {
        int n = tid + j * 256;
        float d = y[n] - mean; loc2 += d * d;
    }
    float var = blockSum(loc2, red, tid) * (1.0f / Hx);
    float w = rsqrtf(var + 1e-5f);
#pragma unroll
    for (int j = 0; j < 4; j++) {
        int n = tid + j * 256;
        g_out1[(size_t)bk * Hx + n] = (y[n] - mean) * w * g1[n] + b1[n];
    }
}

__global__ void ln2tanh_kernel(const float* __restrict__ bp,
                               const float* __restrict__ g2, const float* __restrict__ b2) {
    const int bk = blockIdx.x, tid = threadIdx.x;
    __shared__ float y[Hx];
    __shared__ float red[8];
    float loc = 0.f;
#pragma unroll
    for (int j = 0; j < 4; j++) {
        int n = tid + j * 256;
        float v = bp[n] + g_out1[(size_t)bk * Hx + n];
#pragma unroll
        for (int p = 0; p < SPQ; p++) v += g_pP[((size_t)p * BKx + bk) * Hx + n];
        y[n] = v; loc += v;
    }
    float mean = blockSum(loc, red, tid) * (1.0f / Hx);
    float loc2 = 0.f;
#pragma unroll
    for (int j = 0; j < 4; j++) {
        int n = tid + j * 256;
        float d = y[n] - mean; loc2 += d * d;
    }
    float var = blockSum(loc2, red, tid) * (1.0f / Hx);
    float w = rsqrtf(var + 1e-5f);
#pragma unroll
    for (int j = 0; j < 4; j++) {
        int n = tid + j * 256;
        g_tanh[(size_t)bk * Hx + n] = tanhf((y[n] - mean) * w * g2[n] + b2[n]);
    }
}

// ------------------------------ log-softmax + output ------------------------
__global__ void lsm_kernel(float* __restrict__ out, int step) {
    const int bk = blockIdx.x, tid = threadIdx.x;
    __shared__ float sl[Cx];
    __shared__ float red[8];
    float m = -INFINITY;
    for (int c = tid; c < Cx; c += 256) {
        float v = 0.f;
#pragma unroll
        for (int p = 0; p < SPG; p++) v += g_gP[((size_t)p * BKx + bk) * 2048 + c];
        sl[c] = v;
        m = fmaxf(m, v);
    }
    float M = blockMax(m, red, tid);
    float s = 0.f;
    for (int c = tid; c < Cx; c += 256) s += expf(sl[c] - M);
    float S = blockSum(s, red, tid);
    float lse = logf(S);
    float sc = g_score[bk];
    for (int c = tid; c < Cx; c += 256) {
        float lp = sl[c] - M - lse;
        out[((size_t)step * BKx + bk) * Cx + c] = lp;
        g_cand[(size_t)bk * Cx + c] = sc + lp;
    }
}

// ---------------- single-pass top-3 + beam update + gather ------------------
// Strict total order (value desc, index asc) matches lax.top_k semantics
// (keys unique by index); 3-max selection under a strict total order is
// merge-order-independent, so per-thread lists + shuffle merges are exact.
__device__ __forceinline__ void ins3(float v, int j,
                                     float& v0, int& j0, float& v1, int& j1,
                                     float& v2, int& j2) {
    if (v > v0 || (v == v0 && j < j0)) {
        v2 = v1; j2 = j1; v1 = v0; j1 = j0; v0 = v; j0 = j;
    } else if (v > v1 || (v == v1 && j < j1)) {
        v2 = v1; j2 = j1; v1 = v; j1 = j;
    } else if (v > v2 || (v == v2 && j < j2)) {
        v2 = v; j2 = j;
    }
}

__global__ void topk_gather_kernel() {
    const int b = blockIdx.x, tid = threadIdx.x;
    __shared__ float sv[8][3];
    __shared__ int si[8][3];
    __shared__ int chI[3];
    __shared__ float chV[3];

    float v0 = -INFINITY, v1 = -INFINITY, v2 = -INFINITY;
    int j0 = 0x7fffffff, j1 = 0x7fffffff, j2 = 0x7fffffff;
    for (int j = tid; j < Kb * Cx; j += 256) {
        float v = g_cand[(size_t)(b * Kb + j / Cx) * Cx + (j % Cx)];
        ins3(v, j, v0, j0, v1, j1, v2, j2);
    }
#pragma unroll
    for (int o = 16; o; o >>= 1) {
        float w0 = __shfl_xor_sync(0xffffffffu, v0, o);
        float w1 = __shfl_xor_sync(0xffffffffu, v1, o);
        float w2 = __shfl_xor_sync(0xffffffffu, v2, o);
        int k0 = __shfl_xor_sync(0xffffffffu, j0, o);
        int k1 = __shfl_xor_sync(0xffffffffu, j1, o);
        int k2 = __shfl_xor_sync(0xffffffffu, j2, o);
        ins3(w0, k0, v0, j0, v1, j1, v2, j2);
        ins3(w1, k1, v0, j0, v1, j1, v2, j2);
        ins3(w2, k2, v0, j0, v1, j1, v2, j2);
    }
    if ((tid & 31) == 0) {
        int w = tid >> 5;
        sv[w][0] = v0; sv[w][1] = v1; sv[w][2] = v2;
        si[w][0] = j0; si[w][1] = j1; si[w][2] = j2;
    }
    __syncthreads();
    if (tid == 0) {
        float f0 = -INFINITY, f1 = -INFINITY, f2 = -INFINITY;
        int g0 = 0x7fffffff, g1 = 0x7fffffff, g2 = 0x7fffffff;
#pragma unroll
        for (int w = 0; w < 8; w++)
#pragma unroll
            for (int e = 0; e < 3; e++)
                ins3(sv[w][e], si[w][e], f0, g0, f1, g1, f2, g2);
        chI[0] = g0; chV[0] = f0;
        chI[1] = g1; chV[1] = f1;
        chI[2] = g2; chV[2] = f2;
    }
    __syncthreads();

    if (tid < 3) {
        int j = chI[tid];
        float v = chV[tid];
        int sym = j % Cx;
        g_inp[b * Kb + tid] = sym;
        g_score[b * Kb + tid] = (sym == EOSv) ? NEGV : v;
    }
    __syncthreads();

    // gather h/c (beam sources are intra-batch: block-local, safe)
#pragma unroll
    for (int kb = 0; kb < 3; kb++) {
        int src = b * Kb + chI[kb] / Cx;
        int dstBk = b * Kb + kb;
#pragma unroll
        for (int l = 0; l < 2; l++) {
            size_t dst = ((size_t)l * BKx + dstBk) * Hx;
            size_t so  = ((size_t)l * BKx + src) * Hx;
#pragma unroll
            for (int j = 0; j < 4; j++) {
                int n = tid + j * 256;
                g_h[dst + n] = g_hs[so + n];
                g_c[dst + n] = g_cs[so + n];
            }
        }
    }
}

// ------------------------------ host launcher -------------------------------
extern "C" void kernel_launch(void* const* d_in, const int* in_sizes, int n_in,
                              void* d_out, int out_size) {
    const float* enc  = (const float*)d_in[0];
    const float* emb  = (const float*)d_in[1];
    const float* w_ih = (const float*)d_in[2];
    const float* w_hh = (const float*)d_in[3];
    const float* b_ih = (const float*)d_in[4];
    const float* b_hh = (const float*)d_in[5];
    const float* wq   = (const float*)d_in[6];
    const float* bq   = (const float*)d_in[7];
    const float* wk   = (const float*)d_in[8];
    const float* bk_  = (const float*)d_in[9];
    const float* wv   = (const float*)d_in[10];
    const float* bv   = (const float*)d_in[11];
    const float* ln1g = (const float*)d_in[12];
    const float* ln1b = (const float*)d_in[13];
    const float* wp   = (const float*)d_in[14];
    const float* bp   = (const float*)d_in[15];
    const float* ln2g = (const float*)d_in[16];
    const float* ln2b = (const float*)d_in[17];
    const float* wg   = (const float*)d_in[18];
    float* out = (float*)d_out;

    float *p_h, *p_hs, *p_out1, *p_tanh, *p_gatesP, *p_qP, *p_pP, *p_gP;
    int* p_inp;
    cudaGetSymbolAddress((void**)&p_h, g_h);
    cudaGetSymbolAddress((void**)&p_hs, g_hs);
    cudaGetSymbolAddress((void**)&p_out1, g_out1);
    cudaGetSymbolAddress((void**)&p_tanh, g_tanh);
    cudaGetSymbolAddress((void**)&p_gatesP, g_gatesP);
    cudaGetSymbolAddress((void**)&p_qP, g_qP);
    cudaGetSymbolAddress((void**)&p_pP, g_pP);
    cudaGetSymbolAddress((void**)&p_gP, g_gP);
    cudaGetSymbolAddress((void**)&p_inp, g_inp);

    init_kernel<<<384, 256>>>();
    // two kvproj launches keep ncu -s 5 -c 1 aimed at gemm_lstm
    kvproj_kernel<<<dim3(8, 64), 256>>>(enc, wk, bk_, 0);
    kvproj_kernel<<<dim3(8, 64), 256>>>(enc, wv, bv, 1);

    const size_t WL = (size_t)4096 * Hx;

    for (int t = 0; t < Tx; t++) {
        gemm_lstm<<<dim3(16, SPL), 256>>>(emb, p_inp, w_ih,
                                          p_h, w_hh, Hx / SPL, p_gatesP);
        lstm_point<<<192, 256>>>(0, b_ih, b_hh);
        gemm_lstm<<<dim3(16, SPL), 256>>>(p_hs, nullptr, w_ih + WL,
                                          p_h + BKx * Hx, w_hh + WL,
                                          Hx / SPL, p_gatesP);
        lstm_point<<<192, 256>>>(1, b_ih + 4096, b_hh + 4096);
        gemm_kn<<<dim3(4, SPQ), 256>>>(p_hs + BKx * Hx, wq, Hx / SPQ, Hx, Hx, p_qP);
        attn_kernel<<<dim3(16, 4), 256>>>(bq);
        ln1_kernel<<<48, 256>>>(ln1g, ln1b);
        gemm_kn<<<dim3(4, SPQ), 256>>>(p_out1, wp, Hx / SPQ, Hx, Hx, p_pP);
        ln2tanh_kernel<<<48, 256>>>(bp, ln2g, ln2b);
        gemm_kn<<<dim3(8, SPG), 256>>>(p_tanh, wg, Hx / SPG, Cx, 2048, p_gP);
        lsm_kernel<<<48, 256>>>(out, t);
        topk_gather_kernel<<<16, 256>>>();
    }
    (void)in_sizes; (void)n_in; (void)out_size;
}